// round 7
// baseline (speedup 1.0000x reference)
#include <cuda_runtime.h>
#include <cuda_bf16.h>
#include <cstdint>

#define Bn   2
#define Sn   2048
#define Hn   8
#define DMn  512
#define HDn  64
#define NRn  513
#define BHn  (Bn*Hn)
#define WBS  576     // padded stride for Wb / EvT
#define RSTR 640     // padded rows for Ek
#define NIN  (Bn*Sn*DMn)

// ---------------- scratch ----------------
__device__ float g_Wb[(size_t)BHn*Sn*WBS];     // bucket sums, zero padded

__device__ __nv_bfloat16 g_INh[2*NIN], g_INl[2*NIN];          // query | value splits
__device__ __nv_bfloat16 g_WTh[4*DMn*DMn], g_WTl[4*DMn*DMn];  // Wq,Wk,Wv,Wo transposed [n][k]
__device__ __nv_bfloat16 g_Qh[BHn*Sn*HDn], g_Ql[BHn*Sn*HDn];  // pre-scaled 1/8
__device__ __nv_bfloat16 g_Kh[BHn*Sn*HDn], g_Kl[BHn*Sn*HDn];
__device__ __nv_bfloat16 g_VTh[BHn*HDn*Sn], g_VTl[BHn*HDn*Sn]; // [bh][d][s]
__device__ __nv_bfloat16 g_Oh[BHn*Sn*HDn],  g_Ol[BHn*Sn*HDn];
__device__ __nv_bfloat16 g_Ekh[RSTR*HDn],  g_Ekl[RSTR*HDn];    // [r][d], zero pad
__device__ __nv_bfloat16 g_EvTh[HDn*WBS],  g_EvTl[HDn*WBS];    // [d][r], zero pad

// ============================================================================
// helpers
// ============================================================================
__device__ __forceinline__ uint32_t smem_u32(const void* p) {
    uint32_t a;
    asm("{ .reg .u64 t; cvta.to.shared.u64 t, %1; cvt.u32.u64 %0, t; }"
        : "=r"(a) : "l"(p));
    return a;
}
__device__ __forceinline__ void ldsm_x4(uint32_t& r0, uint32_t& r1,
                                        uint32_t& r2, uint32_t& r3,
                                        uint32_t addr) {
    asm volatile("ldmatrix.sync.aligned.m8n8.x4.shared.b16 {%0,%1,%2,%3}, [%4];"
                 : "=r"(r0), "=r"(r1), "=r"(r2), "=r"(r3) : "r"(addr));
}
__device__ __forceinline__ void mma16816(float* d, const uint32_t* a,
                                         uint32_t b0, uint32_t b1) {
    asm volatile(
        "mma.sync.aligned.m16n8k16.row.col.f32.bf16.bf16.f32 "
        "{%0,%1,%2,%3}, {%4,%5,%6,%7}, {%8,%9}, {%0,%1,%2,%3};"
        : "+f"(d[0]), "+f"(d[1]), "+f"(d[2]), "+f"(d[3])
        : "r"(a[0]), "r"(a[1]), "r"(a[2]), "r"(a[3]), "r"(b0), "r"(b1));
}

#define CP_ASYNC16(dst, src) \
    asm volatile("cp.async.cg.shared.global [%0], [%1], 16;" :: "r"(dst), "l"(src))
#define CP_COMMIT() asm volatile("cp.async.commit_group;" ::: "memory")
#define CP_WAIT(n)  asm volatile("cp.async.wait_group %0;" :: "n"(n) : "memory")

union B4 { __nv_bfloat16 b[4]; uint2 u; };

__device__ __forceinline__ void split1(float x, __nv_bfloat16& h, __nv_bfloat16& l) {
    h = __float2bfloat16(x);
    l = __float2bfloat16(x - __bfloat162float(h));
}
__device__ __forceinline__ void split2(float a, float b, uint32_t& hh, uint32_t& ll) {
    __nv_bfloat16 h0, l0, h1, l1;
    split1(a, h0, l0); split1(b, h1, l1);
    __nv_bfloat162 H; H.x = h0; H.y = h1;
    __nv_bfloat162 L; L.x = l0; L.y = l1;
    hh = *(uint32_t*)&H; ll = *(uint32_t*)&L;
}

#define ASB 144   // padded smem row stride bytes (64 bf16 + 16B pad)

// ============================================================================
// conv kernels
// ============================================================================
__global__ __launch_bounds__(256)
void conv_in_kernel(const float* __restrict__ query,
                    const float* __restrict__ value)
{
    const size_t N4 = NIN/4;
    size_t stride = (size_t)gridDim.x*blockDim.x;
    for (size_t i = (size_t)blockIdx.x*blockDim.x + threadIdx.x; i < N4; i += stride) {
        float4 q = ((const float4*)query)[i];
        B4 h, l;
        split1(q.x, h.b[0], l.b[0]); split1(q.y, h.b[1], l.b[1]);
        split1(q.z, h.b[2], l.b[2]); split1(q.w, h.b[3], l.b[3]);
        *(uint2*)&g_INh[4*i] = h.u; *(uint2*)&g_INl[4*i] = l.u;

        float4 v = ((const float4*)value)[i];
        split1(v.x, h.b[0], l.b[0]); split1(v.y, h.b[1], l.b[1]);
        split1(v.z, h.b[2], l.b[2]); split1(v.w, h.b[3], l.b[3]);
        *(uint2*)&g_INh[NIN + 4*i] = h.u; *(uint2*)&g_INl[NIN + 4*i] = l.u;
    }
}

__global__ __launch_bounds__(256)
void conv_w_kernel(const float* __restrict__ Wq, const float* __restrict__ Wk,
                   const float* __restrict__ Wv, const float* __restrict__ Wo)
{
    __shared__ float t[64][65];
    int w = blockIdx.z;
    const float* W = (w == 0) ? Wq : (w == 1) ? Wk : (w == 2) ? Wv : Wo;
    int k0 = blockIdx.y * 64;
    int n0 = blockIdx.x * 64;
    int tid = threadIdx.x;
    for (int idx = tid; idx < 64*64; idx += 256) {
        int r = idx >> 6, c = idx & 63;
        t[r][c] = W[(size_t)(k0 + r)*DMn + n0 + c];
    }
    __syncthreads();
    for (int idx = tid; idx < 64*32; idx += 256) {
        int nl = idx >> 5, kp = (idx & 31)*2;
        uint32_t hh, ll;
        split2(t[kp][nl], t[kp+1][nl], hh, ll);
        size_t o = (size_t)w*DMn*DMn + (size_t)(n0 + nl)*DMn + k0 + kp;
        *(uint32_t*)&g_WTh[o] = hh;
        *(uint32_t*)&g_WTl[o] = ll;
    }
}

__global__ __launch_bounds__(256)
void conv_misc_kernel(const float* __restrict__ Ek, const float* __restrict__ Ev)
{
    int stride = gridDim.x*blockDim.x;
    int tid = blockIdx.x*blockDim.x + threadIdx.x;
    for (int idx = tid; idx < RSTR*HDn; idx += stride) {
        int r = idx >> 6, d = idx & 63;
        float v = (r < NRn) ? Ek[(size_t)r*HDn + d] : 0.f;
        __nv_bfloat16 h, l; split1(v, h, l);
        g_Ekh[idx] = h; g_Ekl[idx] = l;
    }
    for (int idx = tid; idx < HDn*WBS; idx += stride) {
        int d = idx / WBS, r = idx - d*WBS;
        float v = (r < NRn) ? Ev[(size_t)r*HDn + d] : 0.f;
        __nv_bfloat16 h, l; split1(v, h, l);
        g_EvTh[idx] = h; g_EvTl[idx] = l;
    }
}

// ============================================================================
// proj_mma: cp.async double-buffered. t=0 Q (x1/8), t=1 K, t=2 V (transposed)
// stage layout: st*73728 + {AH 0, AL 18432, BH 36864, BL 55296}
// ============================================================================
#define STAGE 73728
#define PJ_BYTES (2*STAGE)   // 147456

__global__ __launch_bounds__(256)
void proj_mma_kernel()
{
    extern __shared__ char sm[];
    uint32_t sb = smem_u32(sm);
    const int tid  = threadIdx.x;
    const int lane = tid & 31;
    const int warp = tid >> 5;
    const int t  = blockIdx.z;
    const int m0g = blockIdx.y * 128;
    const int n0g = blockIdx.x * 128;

    const __nv_bfloat16* Ah = g_INh + (t ? NIN : 0);
    const __nv_bfloat16* Al = g_INl + (t ? NIN : 0);
    const __nv_bfloat16* Bh = g_WTh + (size_t)t*DMn*DMn;
    const __nv_bfloat16* Bl = g_WTl + (size_t)t*DMn*DMn;

    const int m0 = (warp >> 2) * 64;
    const int n0 = (warp & 3) * 32;
    const uint32_t loff = (uint32_t)((lane & 15)*ASB + (lane >> 4)*16);

    float acc[4][4][4] = {};

    auto prefetch = [&](int kc, int st) {
        uint32_t base = sb + st*STAGE;
        for (int it = tid; it < 1024; it += 256) {
            int r = it >> 3, c = it & 7;
            uint32_t so = (uint32_t)(r*ASB + c*16);
            size_t ga = (size_t)(m0g + r)*DMn + kc*64 + c*8;
            size_t gb = (size_t)(n0g + r)*DMn + kc*64 + c*8;
            CP_ASYNC16(base + so,         (const char*)(Ah + ga));
            CP_ASYNC16(base + 18432 + so, (const char*)(Al + ga));
            CP_ASYNC16(base + 36864 + so, (const char*)(Bh + gb));
            CP_ASYNC16(base + 55296 + so, (const char*)(Bl + gb));
        }
        CP_COMMIT();
    };

    prefetch(0, 0);
    for (int kc = 0; kc < 8; kc++) {
        int st = kc & 1;
        if (kc < 7) { prefetch(kc + 1, st ^ 1); CP_WAIT(1); }
        else        { CP_WAIT(0); }
        __syncthreads();

        uint32_t base = sb + st*STAGE;
        const uint32_t abase[3] = { base, base, base + 18432 };
        const uint32_t bbase[3] = { base + 36864, base + 55296, base + 36864 };
        #pragma unroll
        for (int tt = 0; tt < 3; tt++) {
            #pragma unroll
            for (int kt = 0; kt < 4; kt++) {
                uint32_t koff = kt*32;
                uint32_t a[4][4];
                #pragma unroll
                for (int mi = 0; mi < 4; mi++)
                    ldsm_x4(a[mi][0], a[mi][1], a[mi][2], a[mi][3],
                            abase[tt] + (uint32_t)(m0 + mi*16)*ASB + koff + loff);
                uint32_t b[2][4];
                #pragma unroll
                for (int bi = 0; bi < 2; bi++)
                    ldsm_x4(b[bi][0], b[bi][1], b[bi][2], b[bi][3],
                            bbase[tt] + (uint32_t)(n0 + bi*16)*ASB + koff + loff);
                #pragma unroll
                for (int mi = 0; mi < 4; mi++) {
                    mma16816(acc[mi][0], a[mi], b[0][0], b[0][2]);
                    mma16816(acc[mi][1], a[mi], b[0][1], b[0][3]);
                    mma16816(acc[mi][2], a[mi], b[1][0], b[1][2]);
                    mma16816(acc[mi][3], a[mi], b[1][1], b[1][3]);
                }
            }
        }
        __syncthreads();
    }

    if (t < 2) {
        const float scale = (t == 0) ? 0.125f : 1.0f;
        __nv_bfloat16* Dh = (t == 0) ? g_Qh : g_Kh;
        __nv_bfloat16* Dl = (t == 0) ? g_Ql : g_Kl;
        #pragma unroll
        for (int mi = 0; mi < 4; mi++) {
            #pragma unroll
            for (int rr = 0; rr < 2; rr++) {
                int row = m0g + m0 + mi*16 + rr*8 + (lane >> 2);
                int b = row >> 11, s = row & 2047;
                #pragma unroll
                for (int ni = 0; ni < 4; ni++) {
                    int colg = n0g + n0 + ni*8 + (lane & 3)*2;
                    int h = colg >> 6, d = colg & 63;
                    size_t addr = (((size_t)(b*Hn + h))*Sn + s)*HDn + d;
                    uint32_t hh, ll;
                    split2(acc[mi][ni][rr*2 + 0]*scale, acc[mi][ni][rr*2 + 1]*scale, hh, ll);
                    *(uint32_t*)&Dh[addr] = hh;
                    *(uint32_t*)&Dl[addr] = ll;
                }
            }
        }
    } else {
        // V: stage fp32 tile, transpose-write VT hi/lo
        float* stage = (float*)sm;   // 128x132 floats = 67584 B <= PJ_BYTES
        #pragma unroll
        for (int mi = 0; mi < 4; mi++) {
            #pragma unroll
            for (int rr = 0; rr < 2; rr++) {
                int rl = m0 + mi*16 + rr*8 + (lane >> 2);
                #pragma unroll
                for (int ni = 0; ni < 4; ni++) {
                    int cl = n0 + ni*8 + (lane & 3)*2;
                    *(float2*)&stage[rl*132 + cl] =
                        make_float2(acc[mi][ni][rr*2 + 0], acc[mi][ni][rr*2 + 1]);
                }
            }
        }
        __syncthreads();
        int b  = m0g >> 11;
        int s0 = m0g & 2047;
        for (int idx = tid; idx < 128*64; idx += 256) {
            int c = idx >> 6, sp = idx & 63;
            int sl = sp*2;
            int colg = n0g + c;
            int h = colg >> 6, d = colg & 63;
            uint32_t hh, ll;
            split2(stage[sl*132 + c], stage[(sl+1)*132 + c], hh, ll);
            size_t addr = ((size_t)((b*Hn + h)*HDn + d))*Sn + s0 + sl;
            *(uint32_t*)&g_VTh[addr] = hh;
            *(uint32_t*)&g_VTl[addr] = ll;
        }
    }
}

// ============================================================================
// fused kernel: REL(16x640) + alpha(16x2048) via mma + exact softmax
//               + write p + bucket sums + write Wb.   One CTA = 16 rows.
// ============================================================================
#define FS_A    0                        // float [16][2048]
#define FS_W    (16*2048*4)              // float [16][520]
#define FS_RS   (FS_W + 16*520*4)
#define FS_QH   (FS_RS + 64)
#define FS_QL   (FS_QH + 16*ASB)
#define FS_KH   (FS_QL + 16*ASB)
#define FS_KL   (FS_KH + 128*ASB)
#define FS_BYTES (FS_KL + 128*ASB)       // 205888

__global__ __launch_bounds__(256)
void fused_softmax_kernel(float* __restrict__ attn)
{
    extern __shared__ char sm[];
    uint32_t sb = smem_u32(sm);
    float* A    = (float*)(sm + FS_A);
    float* W    = (float*)(sm + FS_W);
    float* rsum = (float*)(sm + FS_RS);

    const int bh = blockIdx.y;
    const int i0 = blockIdx.x * 16;
    const int tid  = threadIdx.x;
    const int lane = tid & 31;
    const int warp = tid >> 5;
    const uint32_t loff = (uint32_t)((lane & 15)*ASB + (lane >> 4)*16);
    const int n0 = warp * 16;

    // ---- load Q tile (16 x 64 hi/lo) ----
    for (int it = tid; it < 128; it += 256) {
        int r = it >> 3, c = it & 7;
        uint32_t so = (uint32_t)(r*ASB + c*16);
        size_t g = ((size_t)bh*Sn + i0 + r)*HDn + c*8;
        *(uint4*)(sm + FS_QH + so) = *(const uint4*)(g_Qh + g);
        *(uint4*)(sm + FS_QL + so) = *(const uint4*)(g_Ql + g);
    }
    __syncthreads();

    // ---- Q fragments in registers (persist all phases) ----
    uint32_t aH[4][4], aL[4][4];
    #pragma unroll
    for (int kt = 0; kt < 4; kt++) {
        ldsm_x4(aH[kt][0], aH[kt][1], aH[kt][2], aH[kt][3],
                sb + FS_QH + kt*32 + loff);
        ldsm_x4(aL[kt][0], aL[kt][1], aL[kt][2], aL[kt][3],
                sb + FS_QL + kt*32 + loff);
    }
    __syncthreads();

    const int rl0 = lane >> 2;
    const int rl1 = rl0 + 8;

    // ---- Phase 1: REL = Q . Ek^T  (5 chunks of 128 r) -> W ----
    for (int ch = 0; ch < 5; ch++) {
        for (int it = tid; it < 1024; it += 256) {
            int r = it >> 3, c = it & 7;
            uint32_t so = (uint32_t)(r*ASB + c*16);
            size_t g = (size_t)(ch*128 + r)*HDn + c*8;
            *(uint4*)(sm + FS_KH + so) = *(const uint4*)(g_Ekh + g);
            *(uint4*)(sm + FS_KL + so) = *(const uint4*)(g_Ekl + g);
        }
        __syncthreads();

        float acc[2][4] = {};
        #pragma unroll
        for (int kt = 0; kt < 4; kt++) {
            uint32_t koff = kt*32;
            uint32_t b[4], bl[4];
            ldsm_x4(b[0], b[1], b[2], b[3], sb + FS_KH + (uint32_t)n0*ASB + koff + loff);
            ldsm_x4(bl[0], bl[1], bl[2], bl[3], sb + FS_KL + (uint32_t)n0*ASB + koff + loff);
            mma16816(acc[0], aH[kt], b[0],  b[2]);
            mma16816(acc[1], aH[kt], b[1],  b[3]);
            mma16816(acc[0], aL[kt], b[0],  b[2]);
            mma16816(acc[1], aL[kt], b[1],  b[3]);
            mma16816(acc[0], aH[kt], bl[0], bl[2]);
            mma16816(acc[1], aH[kt], bl[1], bl[3]);
        }
        __syncthreads();

        #pragma unroll
        for (int ni = 0; ni < 2; ni++) {
            int col = ch*128 + n0 + ni*8 + (lane & 3)*2;
            if (col <= 518) {
                *(float2*)&W[rl0*520 + col] = make_float2(acc[ni][0], acc[ni][1]);
                *(float2*)&W[rl1*520 + col] = make_float2(acc[ni][2], acc[ni][3]);
            }
        }
    }
    __syncthreads();

    // ---- Phase 2: alpha = Q . K^T + REL gather -> A  (16 chunks of 128 j) ----
    const int ia = i0 + rl0;
    const int ib = i0 + rl1;
    for (int ch = 0; ch < 16; ch++) {
        for (int it = tid; it < 1024; it += 256) {
            int r = it >> 3, c = it & 7;
            uint32_t so = (uint32_t)(r*ASB + c*16);
            size_t g = ((size_t)bh*Sn + ch*128 + r)*HDn + c*8;
            *(uint4*)(sm + FS_KH + so) = *(const uint4*)(g_Kh + g);
            *(uint4*)(sm + FS_KL + so) = *(const uint4*)(g_Kl + g);
        }
        __syncthreads();

        float acc[2][4] = {};
        #pragma unroll
        for (int kt = 0; kt < 4; kt++) {
            uint32_t koff = kt*32;
            uint32_t b[4], bl[4];
            ldsm_x4(b[0], b[1], b[2], b[3], sb + FS_KH + (uint32_t)n0*ASB + koff + loff);
            ldsm_x4(bl[0], bl[1], bl[2], bl[3], sb + FS_KL + (uint32_t)n0*ASB + koff + loff);
            mma16816(acc[0], aH[kt], b[0],  b[2]);
            mma16816(acc[1], aH[kt], b[1],  b[3]);
            mma16816(acc[0], aL[kt], b[0],  b[2]);
            mma16816(acc[1], aL[kt], b[1],  b[3]);
            mma16816(acc[0], aH[kt], bl[0], bl[2]);
            mma16816(acc[1], aH[kt], bl[1], bl[3]);
        }
        __syncthreads();

        #pragma unroll
        for (int ni = 0; ni < 2; ni++) {
            int col = ch*128 + n0 + ni*8 + (lane & 3)*2;
            float2 v0 = make_float2(
                acc[ni][0] + W[rl0*520 + min(256, max(-256, col     - ia)) + 256],
                acc[ni][1] + W[rl0*520 + min(256, max(-256, col + 1 - ia)) + 256]);
            float2 v1 = make_float2(
                acc[ni][2] + W[rl1*520 + min(256, max(-256, col     - ib)) + 256],
                acc[ni][3] + W[rl1*520 + min(256, max(-256, col + 1 - ib)) + 256]);
            *(float2*)&A[rl0*2048 + col] = v0;
            *(float2*)&A[rl1*2048 + col] = v1;
        }
    }
    __syncthreads();

    // ---- softmax: each warp owns 2 rows ----
    #pragma unroll
    for (int rr = 0; rr < 2; rr++) {
        int ii = warp*2 + rr;
        float m = -1e30f;
        for (int j = lane; j < Sn; j += 32) m = fmaxf(m, A[ii*2048 + j]);
        #pragma unroll
        for (int o = 16; o; o >>= 1) m = fmaxf(m, __shfl_xor_sync(0xFFFFFFFFu, m, o));
        float ssum = 0.f;
        for (int j = lane; j < Sn; j += 32) {
            float p = __expf(A[ii*2048 + j] - m);
            A[ii*2048 + j] = p;
            ssum += p;
        }
        #pragma unroll
        for (int o = 16; o; o >>= 1) ssum += __shfl_xor_sync(0xFFFFFFFFu, ssum, o);
        if (lane == 0) rsum[ii] = ssum;
    }
    __syncthreads();

    // ---- normalize + write p ----
    {
        float4* A4 = (float4*)A;
        for (int idx = tid; idx < 16*(Sn/4); idx += 256) {
            int ii = idx >> 9;
            float inv = 1.0f / rsum[ii];
            float4 v = A4[idx];
            v.x *= inv; v.y *= inv; v.z *= inv; v.w *= inv;
            A4[idx] = v;
            ((float4*)(attn + ((size_t)bh*Sn + i0 + ii)*Sn))[idx & 511] = v;
        }
    }
    __syncthreads();

    // ---- bucket sums into W ----
    for (int idx = tid; idx < 16*511; idx += 256) {
        int ii = idx / 511;
        int r  = idx % 511 + 1;
        int j  = i0 + ii + r - 256;
        W[ii*520 + r] = (j >= 0 && j < Sn) ? A[ii*2048 + j] : 0.f;
    }
    #pragma unroll
    for (int rr = 0; rr < 2; rr++) {
        int ii = warp*2 + rr;
        int i  = i0 + ii;
        float s0 = 0.f, s1 = 0.f;
        for (int j = lane; j <= i - 256; j += 32) s0 += A[ii*2048 + j];
        for (int j = i + 256 + lane; j < Sn; j += 32) s1 += A[ii*2048 + j];
        #pragma unroll
        for (int o = 16; o; o >>= 1) {
            s0 += __shfl_xor_sync(0xFFFFFFFFu, s0, o);
            s1 += __shfl_xor_sync(0xFFFFFFFFu, s1, o);
        }
        if (lane == 0) { W[ii*520 + 0] = s0; W[ii*520 + 512] = s1; }
    }
    __syncthreads();

    for (int idx = tid; idx < 16*WBS; idx += 256) {
        int ii = idx / WBS, r = idx - ii*WBS;
        g_Wb[((size_t)bh*Sn + i0 + ii)*WBS + r] = (r < NRn) ? W[ii*520 + r] : 0.f;
    }
}

// ============================================================================
// pv kernel: O[64 x 64] = P·V + Wb·Ev (bf16 3-term), M=64, reg-prefetched
// ============================================================================
#define PVS_AH 0
#define PVS_AL (64*ASB)
#define PVS_VH (2*64*ASB)
#define PVS_VL (3*64*ASB)
#define PVS_BYTES (4*64*ASB)   // 36864

__global__ __launch_bounds__(256)
void pv_kernel(const float* __restrict__ attn)
{
    extern __shared__ char sm[];
    uint32_t sb = smem_u32(sm);
    const int tid  = threadIdx.x;
    const int lane = tid & 31;
    const int warp = tid >> 5;
    const int bh = blockIdx.y;
    const int i0 = blockIdx.x * 64;

    const int m0 = (warp >> 1) * 16;
    const int n0 = (warp & 1) * 32;
    const uint32_t loff = (uint32_t)((lane & 15)*ASB + (lane >> 4)*16);

    const int lr = tid >> 2;          // 0..63 row
    const int lc = (tid & 3) * 16;    // col group (elements)

    float  aReg[16];
    uint4  bHreg[2], bLreg[2];

    auto loadA = [&](int c) {
        const float* src;
        size_t str;
        if (c < 32) { src = attn + ((size_t)bh*Sn + i0)*Sn + c*64;         str = Sn;  }
        else        { src = g_Wb + ((size_t)bh*Sn + i0)*WBS + (c-32)*64;   str = WBS; }
        #pragma unroll
        for (int q = 0; q < 4; q++)
            *(float4*)&aReg[q*4] = *(const float4*)(src + (size_t)lr*str + lc + q*4);
    };
    auto loadB = [&](int c) {
        const __nv_bfloat16 *Bh, *Bl;
        size_t str;
        if (c < 32) { Bh = g_VTh + ((size_t)bh*HDn)*Sn + c*64;
                      Bl = g_VTl + ((size_t)bh*HDn)*Sn + c*64;  str = Sn;  }
        else        { Bh = g_EvTh + (c-32)*64;
                      Bl = g_EvTl + (c-32)*64;                  str = WBS; }
        bHreg[0] = *(const uint4*)(Bh + (size_t)lr*str + lc);
        bHreg[1] = *(const uint4*)(Bh + (size_t)lr*str + lc + 8);
        bLreg[0] = *(const uint4*)(Bl + (size_t)lr*str + lc);
        bLreg[1] = *(const uint4*)(Bl + (size_t)lr*str + lc + 8);
    };

    float acc[4][4] = {};
    const int NCHUNK = 32 + WBS/64;    // 41

    loadA(0); loadB(0);
    for (int c = 0; c < NCHUNK; c++) {
        // store staged regs -> smem (split A to hi/lo)
        {
            uint32_t soA = (uint32_t)(lr*ASB + lc*2);
            #pragma unroll
            for (int q = 0; q < 4; q++) {
                B4 h, l;
                split1(aReg[q*4+0], h.b[0], l.b[0]); split1(aReg[q*4+1], h.b[1], l.b[1]);
                split1(aReg[q*4+2], h.b[2], l.b[2]); split1(aReg[q*4+3], h.b[3], l.b[3]);
                *(uint2*)(sm + PVS_AH + soA + q*8) = h.u;
                *(uint2*)(sm + PVS_AL + soA + q*8) = l.u;
            }
            *(uint4*)(sm + PVS_VH + soA)      = bHreg[0];
            *(uint4*)(sm + PVS_VH + soA + 16) = bHreg[1];
            *(uint4*)(sm + PVS_VL + soA)      = bLreg[0];
            *(uint4*)(sm + PVS_VL + soA + 16) = bLreg[1];
        }
        __syncthreads();

        if (c + 1 < NCHUNK) { loadA(c + 1); loadB(c + 1); }

        const uint32_t abase[3] = { sb + PVS_AH, sb + PVS_AH, sb + PVS_AL };
        const uint32_t bbase[3] = { sb + PVS_VH, sb + PVS_VL, sb + PVS_VH };
        #pragma unroll
        for (int t = 0; t < 3; t++) {
            #pragma unroll
            for (int kt = 0; kt < 4; kt++) {
                uint32_t koff = kt*32;
                uint32_t a[4];
                ldsm_x4(a[0], a[1], a[2], a[3],
                        abase[t] + (uint32_t)m0*ASB + koff + loff);
                uint32_t b[2][4];
                #pragma unroll
                for (int bi = 0; bi < 2; bi++)
                    ldsm_x4(b[bi][0], b[bi][1], b[bi][2], b[bi][3],
                            bbase[t] + (uint32_t)(n0 + bi*16)*ASB + koff + loff);
                mma16816(acc[0], a, b[0][0], b[0][2]);
                mma16816(acc[1], a, b[0][1], b[0][3]);
                mma16816(acc[2], a, b[1][0], b[1][2]);
                mma16816(acc[3], a, b[1][1], b[1][3]);
            }
        }
        __syncthreads();
    }

    // epilogue: split O fragments -> Oh/Ol
    #pragma unroll
    for (int rr = 0; rr < 2; rr++) {
        int row = i0 + m0 + rr*8 + (lane >> 2);
        size_t base = ((size_t)bh*Sn + row)*HDn;
        #pragma unroll
        for (int ni = 0; ni < 4; ni++) {
            int col = n0 + ni*8 + (lane & 3)*2;
            uint32_t hh, ll;
            split2(acc[ni][rr*2 + 0], acc[ni][rr*2 + 1], hh, ll);
            *(uint32_t*)&g_Oh[base + col] = hh;
            *(uint32_t*)&g_Ol[base + col] = ll;
        }
    }
}

// ============================================================================
// outproj_mma: out = O @ Wo + bo (bf16 3-term), cp.async double-buffered
// ============================================================================
__global__ __launch_bounds__(256)
void outproj_mma_kernel(const float* __restrict__ bo, float* __restrict__ out)
{
    extern __shared__ char sm[];
    uint32_t sb = smem_u32(sm);
    const int tid  = threadIdx.x;
    const int lane = tid & 31;
    const int warp = tid >> 5;
    const int m0g = blockIdx.y * 128;
    const int n0g = blockIdx.x * 128;

    const __nv_bfloat16* Bh = g_WTh + (size_t)3*DMn*DMn;
    const __nv_bfloat16* Bl = g_WTl + (size_t)3*DMn*DMn;

    const int m0 = (warp >> 2) * 64;
    const int n0 = (warp & 3) * 32;
    const uint32_t loff = (uint32_t)((lane & 15)*ASB + (lane >> 4)*16);
    const int b = m0g >> 11;

    float acc[4][4][4] = {};

    auto prefetch = [&](int kc, int st) {
        uint32_t base = sb + st*STAGE;
        for (int it = tid; it < 1024; it += 256) {
            int r = it >> 3, c = it & 7;
            uint32_t so = (uint32_t)(r*ASB + c*16);
            int s = (m0g & 2047) + r;
            size_t ga = (((size_t)(b*Hn + kc))*Sn + s)*HDn + c*8;
            size_t gb = (size_t)(n0g + r)*DMn + kc*64 + c*8;
            CP_ASYNC16(base + so,         (const char*)(g_Oh + ga));
            CP_ASYNC16(base + 18432 + so, (const char*)(g_Ol + ga));
            CP_ASYNC16(base + 36864 + so, (const char*)(Bh + gb));
            CP_ASYNC16(base + 55296 + so, (const char*)(Bl + gb));
        }
        CP_COMMIT();
    };

    prefetch(0, 0);
    for (int kc = 0; kc < 8; kc++) {
        int st = kc & 1;
        if (kc < 7) { prefetch(kc + 1, st ^ 1); CP_WAIT(1); }
        else        { CP_WAIT(0); }
        __syncthreads();

        uint32_t base = sb + st*STAGE;
        const uint32_t abase[3] = { base, base, base + 18432 };
        const uint32_t bbase[3] = { base + 36864, base + 55296, base + 36864 };
        #pragma unroll
        for (int tt = 0; tt < 3; tt++) {
            #pragma unroll
            for (int kt = 0; kt < 4; kt++) {
                uint32_t koff = kt*32;
                uint32_t a[4][4];
                #pragma unroll
                for (int mi = 0; mi < 4; mi++)
                    ldsm_x4(a[mi][0], a[mi][1], a[mi][2], a[mi][3],
                            abase[tt] + (uint32_t)(m0 + mi*16)*ASB + koff + loff);
                uint32_t bfr[2][4];
                #pragma unroll
                for (int bi = 0; bi < 2; bi++)
                    ldsm_x4(bfr[bi][0], bfr[bi][1], bfr[bi][2], bfr[bi][3],
                            bbase[tt] + (uint32_t)(n0 + bi*16)*ASB + koff + loff);
                #pragma unroll
                for (int mi = 0; mi < 4; mi++) {
                    mma16816(acc[mi][0], a[mi], bfr[0][0], bfr[0][2]);
                    mma16816(acc[mi][1], a[mi], bfr[0][1], bfr[0][3]);
                    mma16816(acc[mi][2], a[mi], bfr[1][0], bfr[1][2]);
                    mma16816(acc[mi][3], a[mi], bfr[1][1], bfr[1][3]);
                }
            }
        }
        __syncthreads();
    }

    #pragma unroll
    for (int mi = 0; mi < 4; mi++) {
        int row = m0g + m0 + mi*16 + (lane >> 2);
        float* base0 = out + (size_t)row*DMn + n0g;
        float* base1 = base0 + 8*(size_t)DMn;
        #pragma unroll
        for (int ni = 0; ni < 4; ni++) {
            int col = n0 + ni*8 + (lane & 3)*2;
            float b0 = bo[n0g + col], b1 = bo[n0g + col + 1];
            *(float2*)(base0 + col) = make_float2(acc[mi][ni][0] + b0, acc[mi][ni][1] + b1);
            *(float2*)(base1 + col) = make_float2(acc[mi][ni][2] + b0, acc[mi][ni][3] + b1);
        }
    }
}

// ============================================================================
extern "C" void kernel_launch(void* const* d_in, const int* in_sizes, int n_in,
                              void* d_out, int out_size)
{
    const float* query = (const float*)d_in[0];
    const float* value = (const float*)d_in[1];
    const float* Wq    = (const float*)d_in[2];
    const float* Wk    = (const float*)d_in[3];
    const float* Wv    = (const float*)d_in[4];
    const float* Wo    = (const float*)d_in[5];
    const float* bo    = (const float*)d_in[6];
    const float* Ek    = (const float*)d_in[7];
    const float* Ev    = (const float*)d_in[8];
    float* out = (float*)d_out;

    const int OUT_ELEMS = Bn*Sn*DMn;
    float* attn = out + (size_t)OUT_ELEMS;

    cudaFuncSetAttribute(proj_mma_kernel,      cudaFuncAttributeMaxDynamicSharedMemorySize, PJ_BYTES);
    cudaFuncSetAttribute(outproj_mma_kernel,   cudaFuncAttributeMaxDynamicSharedMemorySize, PJ_BYTES);
    cudaFuncSetAttribute(fused_softmax_kernel, cudaFuncAttributeMaxDynamicSharedMemorySize, FS_BYTES);
    cudaFuncSetAttribute(pv_kernel,            cudaFuncAttributeMaxDynamicSharedMemorySize, PVS_BYTES);

    // conversions
    conv_in_kernel<<<512, 256>>>(query, value);
    conv_w_kernel<<<dim3(8, 8, 4), 256>>>(Wq, Wk, Wv, Wo);
    conv_misc_kernel<<<64, 256>>>(Ek, Ev);

    // projections (tensor, pipelined)
    proj_mma_kernel<<<dim3(DMn/128, (Bn*Sn)/128, 3), 256, PJ_BYTES>>>();

    // fused rel + alpha + softmax + bucket sums
    fused_softmax_kernel<<<dim3(Sn/16, BHn), 256, FS_BYTES>>>(attn);

    // O = P·V + Wb·Ev (tensor, M=64, reg-prefetched)
    pv_kernel<<<dim3(Sn/64, BHn), 256, PVS_BYTES>>>(attn);

    // output projection (tensor, pipelined)
    outproj_mma_kernel<<<dim3(DMn/128, (Bn*Sn)/128), 256, PJ_BYTES>>>(bo, out);
}